// round 9
// baseline (speedup 1.0000x reference)
#include <cuda_runtime.h>
#include <math.h>

#define G3 32768
#define NSITE 65536
#define NVIEW 8

typedef unsigned long long ull;

// -------- device scratch (sanctioned: __device__ globals, no allocation) --------
__device__ float g_hbase_buf[64 * NSITE];        // 16 MB
__device__ float g_minv_buf[NSITE];              // 256 KB
__device__ float g_xx_buf[NVIEW * 32 * NSITE];   // 64 MB
__device__ float g_vis2_buf[NVIEW * NSITE];      // 2 MB

__device__ __forceinline__ float elu_f(float x)  { return x > 0.f ? x : (__expf(x) - 1.f); }
__device__ __forceinline__ float sigm_f(float x) { return 1.f / (1.f + __expf(-x)); }

__device__ __forceinline__ ull pk2(float lo, float hi) {
    ull r; asm("mov.b64 %0, {%1, %2};" : "=l"(r) : "f"(lo), "f"(hi)); return r;
}
__device__ __forceinline__ float2 upk2(ull a) {
    float lo, hi; asm("mov.b64 {%0, %1}, %2;" : "=f"(lo), "=f"(hi) : "l"(a));
    return make_float2(lo, hi);
}
__device__ __forceinline__ ull fma2(ull a, ull b, ull c) {
    ull d; asm("fma.rn.f32x2 %0, %1, %2, %3;" : "=l"(d) : "l"(a), "l"(b), "l"(c)); return d;
}
__device__ __forceinline__ ull mul2(ull a, ull b) {
    ull d; asm("mul.rn.f32x2 %0, %1, %2;" : "=l"(d) : "l"(a), "l"(b)); return d;
}
__device__ __forceinline__ ull add2(ull a, ull b) {
    ull d; asm("add.rn.f32x2 %0, %1, %2;" : "=l"(d) : "l"(a), "l"(b)); return d;
}
__device__ __forceinline__ float hsum2(ull a) { float2 f = upk2(a); return f.x + f.y; }

template<int NP>
__device__ __forceinline__ float pdot(const float* __restrict__ wr, const ull* __restrict__ xp) {
    ull a0 = 0ull, a1 = 0ull;
    #pragma unroll
    for (int k = 0; k < NP / 2; ++k) {
        const ulonglong2 w = *reinterpret_cast<const ulonglong2*>(wr + 4 * k);
        a0 = fma2(w.x, xp[2 * k], a0);
        a1 = fma2(w.y, xp[2 * k + 1], a1);
    }
    return hsum2(add2(a0, a1));
}

// Shared helper: compute packed feats fp[16] for one (site, view) from rde MLP + features.
// Weight pointers are the shared copies.
__device__ __forceinline__ void compute_feats(
    const float* __restrict__ features, const float* __restrict__ depth,
    const float* __restrict__ vdir,
    const float* s_rw1, const float* s_rb1, const float* s_rw2, const float* s_rb2,
    int bn, int v, ull* fp /*16*/, float* fv /*32, optional scalar view (may alias)*/)
{
    const float i0 = __ldg(&vdir[(bn * 3 + 0) * G3 + v]);
    const float i1 = __ldg(&vdir[(bn * 3 + 1) * G3 + v]);
    const float i2 = __ldg(&vdir[(bn * 3 + 2) * G3 + v]);
    const float i3 = __ldg(&depth[bn * G3 + v]);

    ull hp8[8];
    #pragma unroll
    for (int o = 0; o < 16; o += 2) {
        const float4 wa = *reinterpret_cast<const float4*>(&s_rw1[o * 4]);
        const float4 wb = *reinterpret_cast<const float4*>(&s_rw1[(o + 1) * 4]);
        const float ha = elu_f(s_rb1[o]     + wa.x * i0 + wa.y * i1 + wa.z * i2 + wa.w * i3);
        const float hb = elu_f(s_rb1[o + 1] + wb.x * i0 + wb.y * i1 + wb.z * i2 + wb.w * i3);
        hp8[o >> 1] = pk2(ha, hb);
    }
    const float* fbase = &features[(bn * 32) * G3 + v];
    #pragma unroll
    for (int j = 0; j < 16; ++j) {
        const float a = __ldg(&fbase[(2 * j) * G3])
                      + elu_f(s_rb2[2 * j] + pdot<8>(&s_rw2[(2 * j) * 16], hp8));
        const float c = __ldg(&fbase[(2 * j + 1) * G3])
                      + elu_f(s_rb2[2 * j + 1] + pdot<8>(&s_rw2[(2 * j + 1) * 16], hp8));
        fp[j] = pk2(a, c);
        if (fv) { fv[2 * j] = a; fv[2 * j + 1] = c; }
    }
}

// ================= Kernel B: per-voxel mean/var -> hbase, minv =================
__global__ __launch_bounds__(128)
void kB_meanvar(
    const float* __restrict__ features, const float* __restrict__ mask,
    const float* __restrict__ depth,    const float* __restrict__ vdir,
    const float* __restrict__ g_rw1, const float* __restrict__ g_rb1,
    const float* __restrict__ g_rw2, const float* __restrict__ g_rb2,
    const float* __restrict__ g_bw1, const float* __restrict__ g_bb1)
{
    __shared__ __align__(16) float s_rw1[16 * 4];
    __shared__ __align__(16) float s_rb1[16];
    __shared__ __align__(16) float s_rw2[32 * 16];
    __shared__ __align__(16) float s_rb2[32];

    const int tid = threadIdx.x;
    for (int i = tid; i < 16 * 4;  i += 128) s_rw1[i] = g_rw1[i];
    if (tid < 16) s_rb1[tid] = g_rb1[tid];
    for (int i = tid; i < 32 * 16; i += 128) s_rw2[i] = g_rw2[i];
    if (tid < 32) s_rb2[tid] = g_rb2[tid];
    __syncthreads();

    const int site = blockIdx.x * 128 + tid;
    const int b = site >> 15;
    const int v = site & (G3 - 1);

    float msum = 0.f;
    #pragma unroll
    for (int n = 0; n < NVIEW; ++n) msum += __ldg(&mask[(b * NVIEW + n) * G3 + v]);
    const float minv = 1.f / (msum + 1e-8f);
    const float ws   = msum * minv;
    g_minv_buf[site] = minv;

    ull A1p[16], A2p[16];
    #pragma unroll
    for (int j = 0; j < 16; ++j) { A1p[j] = 0ull; A2p[j] = 0ull; }

    #pragma unroll 1
    for (int n = 0; n < NVIEW; ++n) {
        const int bn = b * NVIEW + n;
        const float wn = __ldg(&mask[bn * G3 + v]) * minv;
        const ull wn2 = pk2(wn, wn);
        ull fp[16];
        compute_feats(features, depth, vdir, s_rw1, s_rb1, s_rw2, s_rb2, bn, v, fp, nullptr);
        #pragma unroll
        for (int j = 0; j < 16; ++j) {
            A1p[j] = fma2(wn2, fp[j], A1p[j]);
            A2p[j] = fma2(wn2, mul2(fp[j], fp[j]), A2p[j]);
        }
    }

    {
        const float nw = -(2.f - ws);
        const ull nw2 = pk2(nw, nw);
        #pragma unroll
        for (int j = 0; j < 16; ++j) {
            const ull m = A1p[j];
            A2p[j] = fma2(mul2(m, m), nw2, A2p[j]);   // A1p=mean, A2p=var
        }
    }

    #pragma unroll 1
    for (int o = 0; o < 64; ++o) {
        const float* rm = &g_bw1[o * 96];
        g_hbase_buf[o * NSITE + site] =
            __ldg(&g_bb1[o]) + pdot<16>(rm, A1p) + pdot<16>(rm + 32, A2p);
    }
}

// ================= Kernel C: per (voxel, view) MLP stack -> xx, vis2 =================
__global__ __launch_bounds__(128)
void kC_mlp(
    const float* __restrict__ features, const float* __restrict__ mask,
    const float* __restrict__ depth,    const float* __restrict__ vdir,
    const float* __restrict__ g_rw1, const float* __restrict__ g_rb1,
    const float* __restrict__ g_rw2, const float* __restrict__ g_rb2,
    const float* __restrict__ g_bw1, const float* __restrict__ g_bw2, const float* __restrict__ g_bb2,
    const float* __restrict__ g_vw1, const float* __restrict__ g_vb1,
    const float* __restrict__ g_vw2, const float* __restrict__ g_vb2,
    const float* __restrict__ g_v2w1, const float* __restrict__ g_v2b1,
    const float* __restrict__ g_v2w2, const float* __restrict__ g_v2b2)
{
    __shared__ __align__(16) float s_rw1[16 * 4];
    __shared__ __align__(16) float s_rb1[16];
    __shared__ __align__(16) float s_rw2[32 * 16];
    __shared__ __align__(16) float s_rb2[32];
    __shared__ __align__(16) float s_bw1f[64 * 32];
    __shared__ __align__(16) float s_bw2[32 * 64];
    __shared__ __align__(16) float s_bb2[32];
    __shared__ __align__(16) float s_vw1[32 * 32];
    __shared__ __align__(16) float s_vb1[32];
    __shared__ __align__(16) float s_vw2[33 * 32];
    __shared__ __align__(16) float s_vb2[36];
    __shared__ __align__(16) float s_v2w1[32 * 32];
    __shared__ __align__(16) float s_v2b1[32];
    __shared__ __align__(16) float s_v2w2[32];

    const int tid = threadIdx.x;
    for (int i = tid; i < 16 * 4;  i += 128) s_rw1[i] = g_rw1[i];
    if (tid < 16) s_rb1[tid] = g_rb1[tid];
    for (int i = tid; i < 32 * 16; i += 128) s_rw2[i] = g_rw2[i];
    if (tid < 32) s_rb2[tid] = g_rb2[tid];
    for (int i = tid; i < 64 * 32; i += 128) { int o = i >> 5, c = i & 31; s_bw1f[i] = g_bw1[o * 96 + 64 + c]; }
    for (int i = tid; i < 32 * 64; i += 128) s_bw2[i] = g_bw2[i];
    if (tid < 32) s_bb2[tid] = g_bb2[tid];
    for (int i = tid; i < 32 * 32; i += 128) s_vw1[i] = g_vw1[i];
    if (tid < 32) s_vb1[tid] = g_vb1[tid];
    for (int i = tid; i < 33 * 32; i += 128) s_vw2[i] = g_vw2[i];
    if (tid < 33) s_vb2[tid] = g_vb2[tid];
    for (int i = tid; i < 32 * 32; i += 128) s_v2w1[i] = g_v2w1[i];
    if (tid < 32) s_v2b1[tid] = g_v2b1[tid];
    if (tid < 32) s_v2w2[tid] = g_v2w2[tid];
    __syncthreads();

    const int n    = blockIdx.x >> 9;                       // view
    const int site = (blockIdx.x & 511) * 128 + tid;        // (b, voxel)
    const int b = site >> 15;
    const int v = site & (G3 - 1);
    const int bn = b * NVIEW + n;

    const float minv = g_minv_buf[site];
    const float mval = __ldg(&mask[bn * G3 + v]);
    const float wn   = mval * minv;
    const float v2b2 = __ldg(g_v2b2);

    // --- feats (recompute) ---
    ull fp[16];
    compute_feats(features, depth, vdir, s_rw1, s_rb1, s_rw2, s_rb2, bn, v, fp, nullptr);

    // --- base: h = elu(hbase + bw1f.f) ; xx = elu(bb2 + bw2.h), 16-chunked ---
    float xx[32];
    #pragma unroll
    for (int j = 0; j < 32; ++j) xx[j] = s_bb2[j];

    #pragma unroll 1
    for (int oc = 0; oc < 4; ++oc) {
        const int o16 = oc * 16;
        ull hp[8];
        #pragma unroll
        for (int k = 0; k < 16; k += 2) {
            const float ha = elu_f(__ldg(&g_hbase_buf[(o16 + k) * NSITE + site])
                                   + pdot<16>(&s_bw1f[(o16 + k) * 32], fp));
            const float hb = elu_f(__ldg(&g_hbase_buf[(o16 + k + 1) * NSITE + site])
                                   + pdot<16>(&s_bw1f[(o16 + k + 1) * 32], fp));
            hp[k >> 1] = pk2(ha, hb);
        }
        #pragma unroll
        for (int j = 0; j < 32; ++j)
            xx[j] += pdot<8>(&s_bw2[j * 64 + o16], hp);
    }
    ull xxp[16];
    #pragma unroll
    for (int j = 0; j < 16; ++j)
        xxp[j] = pk2(elu_f(xx[2 * j]), elu_f(xx[2 * j + 1]));

    // --- vis ---
    const ull wn2 = pk2(wn, wn);
    ull tp[16];
    #pragma unroll
    for (int j = 0; j < 16; ++j) tp[j] = mul2(xxp[j], wn2);

    ull hvp[16];
    #pragma unroll
    for (int o = 0; o < 32; o += 2) {
        const float a = elu_f(s_vb1[o]     + pdot<16>(&s_vw1[o * 32], tp));
        const float c = elu_f(s_vb1[o + 1] + pdot<16>(&s_vw1[(o + 1) * 32], tp));
        hvp[o >> 1] = pk2(a, c);
    }
    #pragma unroll
    for (int j = 0; j < 32; j += 2) {
        const float a = elu_f(s_vb2[j]     + pdot<16>(&s_vw2[j * 32], hvp));
        const float c = elu_f(s_vb2[j + 1] + pdot<16>(&s_vw2[(j + 1) * 32], hvp));
        xxp[j >> 1] = add2(xxp[j >> 1], pk2(a, c));         // x = x + x_res
    }
    const float va  = s_vb2[32] + pdot<16>(&s_vw2[32 * 32], hvp);
    const float vis = sigm_f(elu_f(va)) * mval;

    // --- vis2 ---
    const ull visd = pk2(vis, vis);
    #pragma unroll
    for (int j = 0; j < 16; ++j) tp[j] = mul2(xxp[j], visd);

    float s2 = v2b2;
    #pragma unroll
    for (int o = 0; o < 32; o += 2) {
        const float a = elu_f(s_v2b1[o]     + pdot<16>(&s_v2w1[o * 32], tp));
        const float c = elu_f(s_v2b1[o + 1] + pdot<16>(&s_v2w1[(o + 1) * 32], tp));
        s2 += s_v2w2[o] * a + s_v2w2[o + 1] * c;
    }
    const float vis2 = sigm_f(s2) * mval;

    // --- write per-view outputs ---
    g_vis2_buf[n * NSITE + site] = vis2;
    float* xo = &g_xx_buf[(n * 32) * NSITE + site];
    #pragma unroll
    for (int j = 0; j < 16; ++j) {
        const float2 q = upk2(xxp[j]);
        xo[(2 * j) * NSITE]     = q.x;
        xo[(2 * j + 1) * NSITE] = q.y;
    }
}

// ================= Kernel D: per-voxel reduction + stat head =================
__global__ __launch_bounds__(128)
void kD_stat(const float* __restrict__ g_sw, const float* __restrict__ g_sb,
             float* __restrict__ out)
{
    __shared__ __align__(16) float s_sw[32 * 68];
    __shared__ __align__(16) float s_sb[32];
    const int tid = threadIdx.x;
    for (int i = tid; i < 32 * 65; i += 128) { int o = i / 65, c = i % 65; s_sw[o * 68 + c] = g_sw[i]; }
    if (tid < 32) s_sb[tid] = g_sb[tid];
    __syncthreads();

    const int site = blockIdx.x * 128 + tid;
    const int b = site >> 15;
    const int v = site & (G3 - 1);

    float S = 0.f;
    ull Up[16], Vvp[16];
    #pragma unroll
    for (int j = 0; j < 16; ++j) { Up[j] = 0ull; Vvp[j] = 0ull; }

    #pragma unroll 1
    for (int n = 0; n < NVIEW; ++n) {
        const float vis2 = __ldg(&g_vis2_buf[n * NSITE + site]);
        S += vis2;
        const ull v2d = pk2(vis2, vis2);
        const float* xo = &g_xx_buf[(n * 32) * NSITE + site];
        #pragma unroll
        for (int j = 0; j < 16; ++j) {
            const ull xp = pk2(__ldg(&xo[(2 * j) * NSITE]), __ldg(&xo[(2 * j + 1) * NSITE]));
            Up[j]  = fma2(v2d, xp, Up[j]);
            Vvp[j] = fma2(v2d, mul2(xp, xp), Vvp[j]);
        }
    }

    const float Sinv  = 1.f / (S + 1e-8f);
    const float w2s   = S * Sinv;
    const float wmean = w2s * 0.125f;
    {
        const ull sd = pk2(Sinv, Sinv);
        const float nw = -(2.f - w2s);
        const ull nw2 = pk2(nw, nw);
        #pragma unroll
        for (int j = 0; j < 16; ++j) {
            const ull m2 = mul2(Up[j], sd);
            Up[j]  = m2;
            Vvp[j] = fma2(mul2(m2, m2), nw2, mul2(Vvp[j], sd));
        }
    }

    #pragma unroll 1
    for (int o = 0; o < 32; ++o) {
        const float* wr = &s_sw[o * 68];
        const float acc = s_sb[o] + pdot<16>(wr, Up) + pdot<16>(wr + 32, Vvp) + wr[64] * wmean;
        out[(b * 32 + o) * G3 + v] = elu_f(acc);
    }
}

extern "C" void kernel_launch(void* const* d_in, const int* in_sizes, int n_in,
                              void* d_out, int out_size) {
    (void)in_sizes; (void)n_in; (void)out_size;
    const float* features = (const float*)d_in[0];
    const float* mask     = (const float*)d_in[1];
    const float* depth    = (const float*)d_in[2];
    const float* vdir     = (const float*)d_in[3];
    const float* rde_w1   = (const float*)d_in[4];
    const float* rde_b1   = (const float*)d_in[5];
    const float* rde_w2   = (const float*)d_in[6];
    const float* rde_b2   = (const float*)d_in[7];
    const float* base_w1  = (const float*)d_in[8];
    const float* base_b1  = (const float*)d_in[9];
    const float* base_w2  = (const float*)d_in[10];
    const float* base_b2  = (const float*)d_in[11];
    const float* vis_w1   = (const float*)d_in[12];
    const float* vis_b1   = (const float*)d_in[13];
    const float* vis_w2   = (const float*)d_in[14];
    const float* vis_b2   = (const float*)d_in[15];
    const float* vis2_w1  = (const float*)d_in[16];
    const float* vis2_b1  = (const float*)d_in[17];
    const float* vis2_w2  = (const float*)d_in[18];
    const float* vis2_b2  = (const float*)d_in[19];
    const float* stat_w   = (const float*)d_in[20];
    const float* stat_b   = (const float*)d_in[21];
    float* out = (float*)d_out;

    kB_meanvar<<<512, 128>>>(features, mask, depth, vdir,
                             rde_w1, rde_b1, rde_w2, rde_b2,
                             base_w1, base_b1);

    kC_mlp<<<4096, 128>>>(features, mask, depth, vdir,
                          rde_w1, rde_b1, rde_w2, rde_b2,
                          base_w1, base_w2, base_b2,
                          vis_w1, vis_b1, vis_w2, vis_b2,
                          vis2_w1, vis2_b1, vis2_w2, vis2_b2);

    kD_stat<<<512, 128>>>(stat_w, stat_b, out);
}